// round 1
// baseline (speedup 1.0000x reference)
#include <cuda_runtime.h>
#include <cuda_bf16.h>

// GaussianSplatting2D: W=H=256, N=1000, C=1.
// Pipeline: preprocess -> per-tile binning (ordered) -> tiled compositing render.

#define IMG_W 256
#define IMG_H 256
#define TILE 16
#define TILES_X (IMG_W / TILE)
#define TILES_Y (IMG_H / TILE)
#define NUM_TILES (TILES_X * TILES_Y)
#define MAX_N 1024
#define Q_CUT 41.0f   // opac<=~0.6 * exp(-41/2) < 8e-10 -> negligible vs 1e-3 tol

// Scratch (no allocation allowed in kernel_launch)
__device__ float4 g_p0[MAX_N];            // (mx, my, ia, 2*ib)
__device__ float4 g_p1[MAX_N];            // (ic, opac, color, 0)
__device__ float4 g_bbox[MAX_N];          // (xmin, xmax, ymin, ymax)
__device__ int    g_tlist[NUM_TILES * MAX_N];
__device__ int    g_tcount[NUM_TILES];

__global__ void preprocess_kernel(const float* __restrict__ means,
                                  const float* __restrict__ quats,
                                  const float* __restrict__ scales,
                                  const float* __restrict__ rgbs,
                                  const float* __restrict__ opacities,
                                  int n) {
    int i = blockIdx.x * blockDim.x + threadIdx.x;
    if (i >= n) return;

    float c, s;
    __sincosf(quats[i], &s, &c);
    float sx2 = scales[i * 2 + 0] * scales[i * 2 + 0];
    float sy2 = scales[i * 2 + 1] * scales[i * 2 + 1];
    float a11 = c * c * sx2 + s * s * sy2;
    float a12 = c * s * (sx2 - sy2);
    float a22 = s * s * sx2 + c * c * sy2;
    float det = a11 * a22 - a12 * a12;
    float inv_det = 1.0f / det;
    float ia =  a22 * inv_det;
    float ib = -a12 * inv_det;
    float ic =  a11 * inv_det;

    float opac  = 1.0f / (1.0f + expf(-opacities[i]));
    float color = 1.0f / (1.0f + expf(-rgbs[i]));

    float mx = means[i * 2 + 0];
    float my = means[i * 2 + 1];

    g_p0[i] = make_float4(mx, my, ia, 2.0f * ib);
    g_p1[i] = make_float4(ic, opac, color, 0.0f);

    // extent of {q <= Q_CUT}: |dx| <= sqrt(Q*a11), |dy| <= sqrt(Q*a22)
    float rx = sqrtf(Q_CUT * a11);
    float ry = sqrtf(Q_CUT * a22);
    g_bbox[i] = make_float4(mx - rx, mx + rx, my - ry, my + ry);
}

__global__ void bin_kernel(int n) {
    int tile = blockIdx.x;
    int tid  = threadIdx.x;
    int lane = tid & 31;
    int w    = tid >> 5;

    float tx0 = (float)((tile % TILES_X) * TILE);
    float tx1 = tx0 + (float)TILE;
    float ty0 = (float)((tile / TILES_X) * TILE);
    float ty1 = ty0 + (float)TILE;

    __shared__ int warpCnt[8];

    int total = 0;
    for (int base = 0; base < n; base += 256) {
        int g = base + tid;
        bool hit = false;
        if (g < n) {
            float4 bb = g_bbox[g];  // xmin, xmax, ymin, ymax
            hit = (bb.x <= tx1) && (bb.y >= tx0) && (bb.z <= ty1) && (bb.w >= ty0);
        }
        unsigned m = __ballot_sync(0xffffffffu, hit);
        __syncthreads();                 // protect warpCnt from previous iter readers
        if (lane == 0) warpCnt[w] = __popc(m);
        __syncthreads();
        int off = total + __popc(m & ((1u << lane) - 1u));
        #pragma unroll
        for (int k = 0; k < 8; k++) {
            int cval = warpCnt[k];
            if (k < w) off += cval;
            total += cval;
        }
        if (hit) g_tlist[tile * MAX_N + off] = g;
    }
    if (tid == 0) g_tcount[tile] = total;
}

__global__ void __launch_bounds__(256) render_kernel(float* __restrict__ out) {
    __shared__ float4 s0[256];
    __shared__ float4 s1[256];

    int tile = blockIdx.x;
    int tid  = threadIdx.x;
    int txi  = tile % TILES_X;
    int tyi  = tile / TILES_X;
    int pxq  = txi * TILE + (tid & (TILE - 1));
    int pyq  = tyi * TILE + (tid >> 4);
    float px = (float)pxq + 0.5f;
    float py = (float)pyq + 0.5f;

    int cnt = g_tcount[tile];
    const int* list = g_tlist + tile * MAX_N;

    float T = 1.0f;
    float acc = 0.0f;

    for (int base = 0; base < cnt; base += 256) {
        int m = cnt - base;
        if (m > 256) m = 256;
        __syncthreads();
        if (tid < m) {
            int g = list[base + tid];
            s0[tid] = g_p0[g];
            s1[tid] = g_p1[g];
        }
        __syncthreads();

        for (int j = 0; j < m; j++) {
            float4 a = s0[j];
            float4 b = s1[j];
            float dx = px - a.x;
            float dy = py - a.y;
            float t0 = a.z * dx + a.w * dy;         // ia*dx + 2ib*dy
            float q  = t0 * dx + b.x * dy * dy;     // + ic*dy^2
            if (q < Q_CUT) {
                float alpha = fminf(b.y * __expf(-0.5f * q), 0.999f);
                acc = fmaf(b.z * alpha, T, acc);
                T *= 1.0f - alpha;
            }
        }
        // all pixels in the block saturated -> remaining weight < 1e-6 absolute
        if (__syncthreads_and(T < 1e-6f)) break;
    }

    out[pyq * IMG_W + pxq] = acc;
}

extern "C" void kernel_launch(void* const* d_in, const int* in_sizes, int n_in,
                              void* d_out, int out_size) {
    const float* means     = (const float*)d_in[0];
    const float* quats     = (const float*)d_in[1];
    const float* scales    = (const float*)d_in[2];
    const float* rgbs      = (const float*)d_in[3];
    const float* opacities = (const float*)d_in[4];
    float* out = (float*)d_out;

    int n = in_sizes[1];  // quats: (N,)
    if (n > MAX_N) n = MAX_N;

    preprocess_kernel<<<(n + 255) / 256, 256>>>(means, quats, scales, rgbs, opacities, n);
    bin_kernel<<<NUM_TILES, 256>>>(n);
    render_kernel<<<NUM_TILES, 256>>>(out);
}

// round 2
// speedup vs baseline: 1.2318x; 1.2318x over previous
#include <cuda_runtime.h>
#include <cuda_bf16.h>

// GaussianSplatting2D fused: per-tile preprocess+bin+composite in ONE kernel.
// W=H=256, N=1000, C=1. 256 tiles of 16x16, one block per tile, one thread per pixel.

#define IMG_W 256
#define IMG_H 256
#define TILE 16
#define TILES_X (IMG_W / TILE)
#define NUM_TILES 256
#define MAX_N 1024
#define Q_CUT 41.0f   // opac<1 * exp(-41/2) < 1.3e-9 -> negligible vs 1e-3 tol

__global__ void __launch_bounds__(256) splat_fused_kernel(
    const float2* __restrict__ means,
    const float*  __restrict__ quats,
    const float2* __restrict__ scales,
    const float*  __restrict__ rgbs,
    const float*  __restrict__ opacities,
    float* __restrict__ out,
    int n)
{
    __shared__ float4 s0[MAX_N];   // (mx, my, ia, 2*ib)
    __shared__ float4 s1[MAX_N];   // (ic, opac, color, -)
    __shared__ int warpCnt[8];

    int tile = blockIdx.x;
    int tid  = threadIdx.x;
    int lane = tid & 31;
    int w    = tid >> 5;

    int txi = tile % TILES_X;
    int tyi = tile / TILES_X;
    float tx0 = (float)(txi * TILE);
    float tx1 = tx0 + (float)TILE;
    float ty0 = (float)(tyi * TILE);
    float ty1 = ty0 + (float)TILE;

    // ---- Phase A: preprocess + ordered compaction into smem ----
    int total = 0;
    for (int base = 0; base < n; base += 256) {
        int i = base + tid;
        bool hit = false;
        float4 p0, p1;
        if (i < n) {
            float2 mn = means[i];
            float2 sc = scales[i];
            float c, s;
            __sincosf(quats[i], &s, &c);
            float sx2 = sc.x * sc.x;
            float sy2 = sc.y * sc.y;
            float a11 = c * c * sx2 + s * s * sy2;
            float a12 = c * s * (sx2 - sy2);
            float a22 = s * s * sx2 + c * c * sy2;
            float inv_det = 1.0f / (a11 * a22 - a12 * a12);
            float ia =  a22 * inv_det;
            float ib = -a12 * inv_det;
            float ic =  a11 * inv_det;

            // bbox of {q <= Q_CUT}
            float rx = sqrtf(Q_CUT * a11);
            float ry = sqrtf(Q_CUT * a22);
            hit = (mn.x - rx <= tx1) && (mn.x + rx >= tx0) &&
                  (mn.y - ry <= ty1) && (mn.y + ry >= ty0);
            if (hit) {
                float opac  = 1.0f / (1.0f + __expf(-opacities[i]));
                float color = 1.0f / (1.0f + __expf(-rgbs[i]));
                p0 = make_float4(mn.x, mn.y, ia, 2.0f * ib);
                p1 = make_float4(ic, opac, color, 0.0f);
            }
        }
        unsigned m = __ballot_sync(0xffffffffu, hit);
        __syncthreads();                     // warpCnt reuse hazard
        if (lane == 0) warpCnt[w] = __popc(m);
        __syncthreads();
        int off = total + __popc(m & ((1u << lane) - 1u));
        #pragma unroll
        for (int k = 0; k < 8; k++) {
            int cval = warpCnt[k];
            if (k < w) off += cval;
            total += cval;
        }
        if (hit) { s0[off] = p0; s1[off] = p1; }
    }
    __syncthreads();

    // ---- Phase B: front-to-back compositing over compacted smem list ----
    int pxq = txi * TILE + (tid & (TILE - 1));
    int pyq = tyi * TILE + (tid >> 4);
    float px = (float)pxq + 0.5f;
    float py = (float)pyq + 0.5f;

    float T = 1.0f;
    float acc = 0.0f;

    for (int base = 0; base < total; base += 128) {
        int mcnt = total - base;
        if (mcnt > 128) mcnt = 128;
        for (int j = base; j < base + mcnt; j++) {
            float4 a = s0[j];
            float4 b = s1[j];
            float dx = px - a.x;
            float dy = py - a.y;
            float t0 = a.z * dx + a.w * dy;      // ia*dx + 2ib*dy
            float q  = t0 * dx + b.x * dy * dy;  // + ic*dy^2
            if (q < Q_CUT) {
                float alpha = fminf(b.y * __expf(-0.5f * q), 0.999f);
                acc = fmaf(b.z * alpha, T, acc);
                T *= 1.0f - alpha;
            }
        }
        if (base + 128 < total) {
            if (__syncthreads_and(T < 1e-6f)) break;  // remaining contribution < tol
        }
    }

    out[pyq * IMG_W + pxq] = acc;
}

extern "C" void kernel_launch(void* const* d_in, const int* in_sizes, int n_in,
                              void* d_out, int out_size) {
    const float2* means     = (const float2*)d_in[0];
    const float*  quats     = (const float*)d_in[1];
    const float2* scales    = (const float2*)d_in[2];
    const float*  rgbs      = (const float*)d_in[3];
    const float*  opacities = (const float*)d_in[4];
    float* out = (float*)d_out;

    int n = in_sizes[1];  // quats: (N,)
    if (n > MAX_N) n = MAX_N;

    splat_fused_kernel<<<NUM_TILES, 256>>>(means, quats, scales, rgbs, opacities, out, n);
}

// round 3
// speedup vs baseline: 1.3867x; 1.1257x over previous
#include <cuda_runtime.h>
#include <cuda_bf16.h>

// GaussianSplatting2D fused, split-transmittance parallel.
// 512 tiles of 16x8 px; block = 512 threads = 4 partitions x 128 pixels.
// Each partition composites a contiguous quarter of the tile's ordered
// gaussian list; exact combine: acc = a0 + T0*(a1 + T1*(a2 + T2*a3)).

#define IMG_W 256
#define IMG_H 256
#define TILE_W 16
#define TILE_H 8
#define TILES_X (IMG_W / TILE_W)   // 16
#define TILES_Y (IMG_H / TILE_H)   // 32
#define NUM_TILES (TILES_X * TILES_Y)  // 512
#define PIX (TILE_W * TILE_H)      // 128
#define NPART 4
#define THREADS (PIX * NPART)      // 512
#define MAX_N 1024
#define Q_CUT 41.0f                // exp(-41/2)*0.6 < 8e-10, negligible vs 1e-3 tol

__global__ void __launch_bounds__(THREADS) splat_kernel(
    const float2* __restrict__ means,
    const float*  __restrict__ quats,
    const float2* __restrict__ scales,
    const float*  __restrict__ rgbs,
    const float*  __restrict__ opacities,
    float* __restrict__ out,
    int n)
{
    __shared__ float4 s0[MAX_N];       // (mx, my, -0.5*ia, -0.5*2ib)
    __shared__ float4 s1[MAX_N];       // (-0.5*ic, opac, opac*color, -)
    __shared__ int    warpCnt[16];
    __shared__ float2 sComb[NPART][PIX];   // (acc_p, T_p)

    int tile = blockIdx.x;
    int tid  = threadIdx.x;
    int lane = tid & 31;
    int w    = tid >> 5;

    int txi = tile % TILES_X;
    int tyi = tile / TILES_X;
    float tx0 = (float)(txi * TILE_W);
    float tx1 = tx0 + (float)TILE_W;
    float ty0 = (float)(tyi * TILE_H);
    float ty1 = ty0 + (float)TILE_H;

    // ---- Phase A: preprocess + ordered ballot-compaction into smem ----
    int total = 0;
    for (int base = 0; base < n; base += THREADS) {
        int i = base + tid;
        bool hit = false;
        float4 p0, p1;
        if (i < n) {
            float2 mn = means[i];
            float2 sc = scales[i];
            float c, s;
            __sincosf(quats[i], &s, &c);
            float sx2 = sc.x * sc.x;
            float sy2 = sc.y * sc.y;
            float a11 = c * c * sx2 + s * s * sy2;
            float a12 = c * s * (sx2 - sy2);
            float a22 = s * s * sx2 + c * c * sy2;
            float inv_det = 1.0f / (a11 * a22 - a12 * a12);
            float rx = sqrtf(Q_CUT * a11);
            float ry = sqrtf(Q_CUT * a22);
            hit = (mn.x - rx <= tx1) && (mn.x + rx >= tx0) &&
                  (mn.y - ry <= ty1) && (mn.y + ry >= ty0);
            if (hit) {
                float ia =  a22 * inv_det;
                float ib = -a12 * inv_det;
                float ic =  a11 * inv_det;
                float opac  = 1.0f / (1.0f + __expf(-opacities[i]));
                float color = 1.0f / (1.0f + __expf(-rgbs[i]));
                // fold the -0.5 of exp(-q/2) into the coefficients
                p0 = make_float4(mn.x, mn.y, -0.5f * ia, -ib);
                p1 = make_float4(-0.5f * ic, opac, opac * color, 0.0f);
            }
        }
        unsigned m = __ballot_sync(0xffffffffu, hit);
        __syncthreads();
        if (lane == 0) warpCnt[w] = __popc(m);
        __syncthreads();
        int off = total + __popc(m & ((1u << lane) - 1u));
        #pragma unroll
        for (int k = 0; k < 16; k++) {
            int cval = warpCnt[k];
            if (k < w) off += cval;
            total += cval;
        }
        if (hit) { s0[off] = p0; s1[off] = p1; }
    }
    __syncthreads();

    // ---- Phase B: each partition composites its quarter of the list ----
    int part = tid >> 7;          // 0..3
    int ptid = tid & (PIX - 1);   // pixel within tile
    int pxq  = txi * TILE_W + (ptid & (TILE_W - 1));
    int pyq  = tyi * TILE_H + (ptid >> 4);
    float px = (float)pxq + 0.5f;
    float py = (float)pyq + 0.5f;

    int len = (total + NPART - 1) >> 2;
    int jb  = part * len;
    int je  = jb + len;
    if (je > total) je = total;

    float T = 1.0f;
    float acc = 0.0f;

    for (int cb = jb; cb < je; cb += 32) {
        int ce = cb + 32; if (ce > je) ce = je;
        for (int j = cb; j < ce; j++) {
            float4 a = s0[j];
            float4 b = s1[j];
            float dx = px - a.x;
            float dy = py - a.y;
            float t0 = a.z * dx + a.w * dy;
            float q  = t0 * dx + b.x * dy * dy;    // = -0.5 * quadform
            if (q > -0.5f * Q_CUT) {
                float e = __expf(q);               // alpha = opac*e (never clamps: opac<0.6)
                acc = fmaf(b.z * e, T, acc);       // += color*alpha*T
                T   = fmaf(-b.y * e, T, T);        // *= 1-alpha
            }
        }
        if (ce < je && __all_sync(0xffffffffu, T < 1e-6f)) break;
    }

    sComb[part][ptid] = make_float2(acc, T);
    __syncthreads();

    // ---- Combine: acc = a0 + T0*(a1 + T1*(a2 + T2*a3)) ----
    if (tid < PIX) {
        float2 c0 = sComb[0][tid];
        float2 c1 = sComb[1][tid];
        float2 c2 = sComb[2][tid];
        float2 c3 = sComb[3][tid];
        float r = fmaf(c2.y, c3.x, c2.x);   // a2 + T2*a3
        r = fmaf(c1.y, r, c1.x);            // a1 + T1*(...)
        r = fmaf(c0.y, r, c0.x);            // a0 + T0*(...)
        int opx = txi * TILE_W + (tid & (TILE_W - 1));
        int opy = tyi * TILE_H + (tid >> 4);
        out[opy * IMG_W + opx] = r;
    }
}

extern "C" void kernel_launch(void* const* d_in, const int* in_sizes, int n_in,
                              void* d_out, int out_size) {
    const float2* means     = (const float2*)d_in[0];
    const float*  quats     = (const float*)d_in[1];
    const float2* scales    = (const float2*)d_in[2];
    const float*  rgbs      = (const float*)d_in[3];
    const float*  opacities = (const float*)d_in[4];
    float* out = (float*)d_out;

    int n = in_sizes[1];
    if (n > MAX_N) n = MAX_N;

    splat_kernel<<<NUM_TILES, THREADS>>>(means, quats, scales, rgbs, opacities, out, n);
}

// round 4
// speedup vs baseline: 1.5456x; 1.1146x over previous
#include <cuda_runtime.h>
#include <cuda_bf16.h>

// GaussianSplatting2D: k1 preprocess (once) + fused bin/composite render.
// 512 tiles of 16x8 px; render block = 512 threads = 4 partitions x 128 pixels.
// Exact split-transmittance combine: acc = a0 + T0*(a1 + T1*(a2 + T2*a3)).

#define IMG_W 256
#define IMG_H 256
#define TILE_W 16
#define TILE_H 8
#define TILES_X (IMG_W / TILE_W)       // 16
#define NUM_TILES 512
#define PIX (TILE_W * TILE_H)          // 128
#define NPART 4
#define THREADS (PIX * NPART)          // 512
#define MAX_N 1024
#define Q_CUT 30.0f                    // cut alphas < 0.6*exp(-15) ~ 1.8e-7 each
#define LOG2E 1.4426950408889634f

__device__ float4 g_p0[MAX_N];   // (mx, my, az=-0.5*ia*log2e, aw=-ib*log2e)
__device__ float4 g_p1[MAX_N];   // (bx=-0.5*ic*log2e, opac, opac*color, 0)
__device__ float4 g_bbox[MAX_N]; // (xmin, xmax, ymin, ymax)

__global__ void preprocess_kernel(const float2* __restrict__ means,
                                  const float*  __restrict__ quats,
                                  const float2* __restrict__ scales,
                                  const float*  __restrict__ rgbs,
                                  const float*  __restrict__ opacities,
                                  int n) {
    int i = blockIdx.x * blockDim.x + threadIdx.x;
    if (i >= n) return;
    float2 mn = means[i];
    float2 sc = scales[i];
    float c, s;
    __sincosf(quats[i], &s, &c);
    float sx2 = sc.x * sc.x, sy2 = sc.y * sc.y;
    float a11 = c * c * sx2 + s * s * sy2;
    float a12 = c * s * (sx2 - sy2);
    float a22 = s * s * sx2 + c * c * sy2;
    float inv_det = 1.0f / (a11 * a22 - a12 * a12);
    float ia =  a22 * inv_det;
    float ib = -a12 * inv_det;
    float ic =  a11 * inv_det;
    float opac  = 1.0f / (1.0f + __expf(-opacities[i]));
    float color = 1.0f / (1.0f + __expf(-rgbs[i]));
    g_p0[i] = make_float4(mn.x, mn.y, -0.5f * LOG2E * ia, -LOG2E * ib);
    g_p1[i] = make_float4(-0.5f * LOG2E * ic, opac, opac * color, 0.0f);
    float rx = sqrtf(Q_CUT * a11);
    float ry = sqrtf(Q_CUT * a22);
    g_bbox[i] = make_float4(mn.x - rx, mn.x + rx, mn.y - ry, mn.y + ry);
}

__global__ void __launch_bounds__(THREADS) render_kernel(float* __restrict__ out, int n) {
    __shared__ float4 s0[MAX_N];
    __shared__ float4 s1[MAX_N];
    __shared__ int    sCnt[16];
    __shared__ int    sOff[16];
    __shared__ int    sTot;
    __shared__ float2 sComb[NPART][PIX];

    int tile = blockIdx.x;
    int tid  = threadIdx.x;
    int lane = tid & 31;
    int w    = tid >> 5;
    unsigned lmask = (1u << lane) - 1u;

    int txi = tile % TILES_X;
    int tyi = tile / TILES_X;
    float tx0 = (float)(txi * TILE_W), tx1 = tx0 + (float)TILE_W;
    float ty0 = (float)(tyi * TILE_H), ty1 = ty0 + (float)TILE_H;

    // ---- Phase A: ordered compaction of precomputed gaussians into smem ----
    int total = 0;
    for (int base = 0; base < n; base += THREADS) {
        int i = base + tid;
        bool hit = false;
        if (i < n) {
            float4 bb = g_bbox[i];
            hit = (bb.x <= tx1) && (bb.y >= tx0) && (bb.z <= ty1) && (bb.w >= ty0);
        }
        unsigned m = __ballot_sync(0xffffffffu, hit);
        if (lane == 0) sCnt[w] = __popc(m);
        __syncthreads();
        if (tid < 16) {
            int v = sCnt[tid];
            int x = v;
            #pragma unroll
            for (int d = 1; d < 16; d <<= 1) {
                int y = __shfl_up_sync(0x0000ffffu, x, d);
                if (tid >= d) x += y;
            }
            sOff[tid] = x - v;
            if (tid == 15) sTot = x;
        }
        __syncthreads();
        if (hit) {
            int off = total + sOff[w] + __popc(m & lmask);
            s0[off] = g_p0[i];
            s1[off] = g_p1[i];
        }
        total += sTot;
        __syncthreads();   // protect sCnt/sOff/sTot before next chunk rewrites
    }

    // pad list to a multiple of 128 with no-op entries (all zeros)
    int padded = (total + 127) & ~127;
    float4 z = make_float4(0.f, 0.f, 0.f, 0.f);
    for (int j = total + tid; j < padded; j += THREADS) { s0[j] = z; s1[j] = z; }
    __syncthreads();

    // ---- Phase B: branchless compositing, 4-way split over the list ----
    int part = tid >> 7;
    int ptid = tid & (PIX - 1);
    int pxq  = txi * TILE_W + (ptid & (TILE_W - 1));
    int pyq  = tyi * TILE_H + (ptid >> 4);
    float px = (float)pxq + 0.5f;
    float py = (float)pyq + 0.5f;

    int len = padded >> 2;           // multiple of 32
    int jb  = part * len;
    int je  = jb + len;

    float T = 1.0f, acc = 0.0f;

    for (int cb = jb; cb < je; cb += 32) {
        #pragma unroll 4
        for (int j = cb; j < cb + 32; j++) {
            float4 a = s0[j];
            float4 b = s1[j];
            float dx = px - a.x;
            float dy = py - a.y;
            float t0 = fmaf(a.w, dy, a.z * dx);
            float q  = fmaf(t0, dx, b.x * dy * dy);  // already scaled by -0.5*log2e
            float e;
            asm("ex2.approx.ftz.f32 %0, %1;" : "=f"(e) : "f"(q));
            acc = fmaf(b.z * e, T, acc);             // += color*alpha*T
            T   = fmaf(-b.y * e, T, T);              // *= (1 - alpha)
        }
        if (cb + 32 < je && __all_sync(0xffffffffu, T < 1e-6f)) break;
    }

    sComb[part][ptid] = make_float2(acc, T);
    __syncthreads();

    // ---- Combine ----
    if (tid < PIX) {
        float2 c0 = sComb[0][tid];
        float2 c1 = sComb[1][tid];
        float2 c2 = sComb[2][tid];
        float2 c3 = sComb[3][tid];
        float r = fmaf(c2.y, c3.x, c2.x);
        r = fmaf(c1.y, r, c1.x);
        r = fmaf(c0.y, r, c0.x);
        int opx = txi * TILE_W + (tid & (TILE_W - 1));
        int opy = tyi * TILE_H + (tid >> 4);
        out[opy * IMG_W + opx] = r;
    }
}

extern "C" void kernel_launch(void* const* d_in, const int* in_sizes, int n_in,
                              void* d_out, int out_size) {
    const float2* means     = (const float2*)d_in[0];
    const float*  quats     = (const float*)d_in[1];
    const float2* scales    = (const float2*)d_in[2];
    const float*  rgbs      = (const float*)d_in[3];
    const float*  opacities = (const float*)d_in[4];
    float* out = (float*)d_out;

    int n = in_sizes[1];
    if (n > MAX_N) n = MAX_N;

    preprocess_kernel<<<(n + 255) / 256, 256>>>(means, quats, scales, rgbs, opacities, n);
    render_kernel<<<NUM_TILES, THREADS>>>(out, n);
}